// round 10
// baseline (speedup 1.0000x reference)
#include <cuda_runtime.h>
#include <cuda_bf16.h>
#include <cstdint>

// ---------------------------------------------------------------------------
// StateTransitionModel (2-layer Mamba), round 10:
//   All GEMM operands pre-split to bf16 hi/lo (presplit kernel + producer
//   epilogues); GEMMs and xdt stage-1 become pure-bf16 cp.async pipelines.
//   Scan kernels unchanged from R9 (proven).
// ---------------------------------------------------------------------------

#define LOG2E  1.4426950408889634f
#define LN2    0.6931471805599453f

static const int BATCH   = 2;
static const int SEQ     = 4096;
static const int ROWS    = BATCH * SEQ;   // 8192
static const int DMODEL  = 256;
static const int DINNER  = 512;
static const int DSTATE  = 16;
static const int XDBL_P  = 64;
static const int PCHUNK  = 8;
static const int CLEN    = SEQ / PCHUNK;  // 512

// fp32 scratch
__device__ float g_xz  [ROWS * 2 * DINNER];
__device__ float g_xs  [ROWS * DINNER];
__device__ float g_gs  [ROWS * DINNER];
__device__ float g_xdbl[ROWS * XDBL_P];
__device__ float g_dt  [ROWS * DINNER];
__device__ float g_hf  [BATCH * PCHUNK * DINNER * DSTATE];
__device__ float g_dec [BATCH * PCHUNK * DINNER * DSTATE];

// bf16 hi/lo pairs (split representation of fp32 tensors)
__device__ __align__(16) __nv_bfloat16 g_zh [ROWS * DMODEL];
__device__ __align__(16) __nv_bfloat16 g_zl [ROWS * DMODEL];
__device__ __align__(16) __nv_bfloat16 g_zbh[ROWS * DMODEL];   // layer-1 input
__device__ __align__(16) __nv_bfloat16 g_zbl[ROWS * DMODEL];
__device__ __align__(16) __nv_bfloat16 g_xsh[ROWS * DINNER];
__device__ __align__(16) __nv_bfloat16 g_xsl[ROWS * DINNER];
__device__ __align__(16) __nv_bfloat16 g_ygh[ROWS * DINNER];
__device__ __align__(16) __nv_bfloat16 g_ygl[ROWS * DINNER];
__device__ __align__(16) __nv_bfloat16 g_wih[2 * 1024 * DMODEL];
__device__ __align__(16) __nv_bfloat16 g_wil[2 * 1024 * DMODEL];
__device__ __align__(16) __nv_bfloat16 g_woh[2 * DMODEL * DINNER];
__device__ __align__(16) __nv_bfloat16 g_wol[2 * DMODEL * DINNER];
__device__ __align__(16) __nv_bfloat16 g_xph[2 * 64 * DINNER];  // 64-row padded
__device__ __align__(16) __nv_bfloat16 g_xpl[2 * 64 * DINNER];

// ---------------------------------------------------------------- intrinsics
__device__ __forceinline__ float ex2f(float x) {
    float y; asm("ex2.approx.f32 %0, %1;" : "=f"(y) : "f"(x)); return y;
}
__device__ __forceinline__ float lg2f(float x) {
    float y; asm("lg2.approx.f32 %0, %1;" : "=f"(y) : "f"(x)); return y;
}
__device__ __forceinline__ float rcpf(float x) {
    float y; asm("rcp.approx.f32 %0, %1;" : "=f"(y) : "f"(x)); return y;
}
__device__ __forceinline__ float siluf(float x) {
    return x * rcpf(1.f + ex2f(-x * LOG2E));
}
__device__ __forceinline__ float softplusf(float x) {
    return (x > 20.f) ? x : lg2f(1.f + ex2f(x * LOG2E)) * LN2;
}
__device__ __forceinline__ void cp16(void* dst, const void* src) {
    unsigned d = (unsigned)__cvta_generic_to_shared(dst);
    asm volatile("cp.async.ca.shared.global [%0], [%1], 16;" :: "r"(d), "l"(src));
}
#define CP_COMMIT() asm volatile("cp.async.commit_group;")
#define CP_WAIT1()  asm volatile("cp.async.wait_group 1;")
__device__ __forceinline__ void mma_bf16(float* c, const uint32_t* a,
                                         const uint32_t* b) {
    asm volatile(
        "mma.sync.aligned.m16n8k16.row.col.f32.bf16.bf16.f32 "
        "{%0,%1,%2,%3}, {%4,%5,%6,%7}, {%8,%9}, {%0,%1,%2,%3};"
        : "+f"(c[0]), "+f"(c[1]), "+f"(c[2]), "+f"(c[3])
        : "r"(a[0]), "r"(a[1]), "r"(a[2]), "r"(a[3]), "r"(b[0]), "r"(b[1]));
}
__device__ __forceinline__ void ldm_x4(uint32_t* r, uint32_t addr) {
    asm volatile(
        "ldmatrix.sync.aligned.m8n8.x4.shared.b16 {%0,%1,%2,%3}, [%4];"
        : "=r"(r[0]), "=r"(r[1]), "=r"(r[2]), "=r"(r[3]) : "r"(addr));
}
__device__ __forceinline__ void split4(float4 v, uint32_t& h0, uint32_t& h1,
                                       uint32_t& l0, uint32_t& l1) {
    __nv_bfloat162 a = __floats2bfloat162_rn(v.x, v.y);
    __nv_bfloat162 b = __floats2bfloat162_rn(v.z, v.w);
    float rx = v.x - __bfloat162float(a.x);
    float ry = v.y - __bfloat162float(a.y);
    float rz = v.z - __bfloat162float(b.x);
    float rw = v.w - __bfloat162float(b.y);
    __nv_bfloat162 c = __floats2bfloat162_rn(rx, ry);
    __nv_bfloat162 d = __floats2bfloat162_rn(rz, rw);
    h0 = *(uint32_t*)&a; h1 = *(uint32_t*)&b;
    l0 = *(uint32_t*)&c; l1 = *(uint32_t*)&d;
}
__device__ __forceinline__ uint32_t smem_addr(const void* p) {
    uint32_t a;
    asm("{ .reg .u64 t; cvta.to.shared.u64 t, %1; cvt.u32.u64 %0, t; }"
        : "=r"(a) : "l"(p));
    return a;
}

// --------------------------------------------- presplit: fp32 -> bf16 hi/lo
// segments (float4 units): z[0,524288) inw[524288,655360) outw[655360,720896)
// xpw l0 [720896,729088) xpw l1 [729088,737280)
__global__ void __launch_bounds__(256) presplit_k(
    const float* __restrict__ z, const float* __restrict__ inw,
    const float* __restrict__ outw, const float* __restrict__ xpw)
{
    int i = blockIdx.x * 256 + threadIdx.x;
    float4 v = make_float4(0.f, 0.f, 0.f, 0.f);
    __nv_bfloat16 *dh, *dl;
    long off;
    if (i < 524288) {
        v = *(const float4*)(z + (size_t)i * 4);
        dh = g_zh; dl = g_zl; off = i;
    } else if (i < 655360) {
        long j = i - 524288;
        v = *(const float4*)(inw + j * 4);
        dh = g_wih; dl = g_wil; off = j;
    } else if (i < 720896) {
        long j = i - 655360;
        v = *(const float4*)(outw + j * 4);
        dh = g_woh; dl = g_wol; off = j;
    } else {
        long j = i - 720896;           // 0..16383, two layers of 8192
        long l = j >> 13, k = j & 8191;
        if (k < 6144)                  // 48 real rows of 512 = 6144 float4
            v = *(const float4*)(xpw + l * 24576 + k * 4);
        dh = g_xph; dl = g_xpl; off = j;
    }
    uint32_t h0, h1, l0, l1;
    split4(v, h0, h1, l0, l1);
    *(uint2*)&dh[off * 4] = make_uint2(h0, h1);
    *(uint2*)&dl[off * 4] = make_uint2(l0, l1);
}

// -------------------------------------- pure-bf16 split GEMM (NT=128, NT fix)
// C[M,N] = A @ W^T with A,W given as bf16 hi/lo pairs. cp.async double-buffer,
// ldmatrix-fed, 3-MMA split accumulate. OUTMODE 0: f32 C. 1: bf16 hi/lo C.
static const int KSTR = 20;      // padded row stride (b32 words) = 80B

template<int THREADS, int OUTMODE>
__global__ void __launch_bounds__(THREADS) gemm_bb(
    const __nv_bfloat16* __restrict__ Ah, const __nv_bfloat16* __restrict__ Al,
    const __nv_bfloat16* __restrict__ Wh, const __nv_bfloat16* __restrict__ Wl,
    float* __restrict__ C, __nv_bfloat16* __restrict__ Ch,
    __nv_bfloat16* __restrict__ Cl, int N, int K)
{
    extern __shared__ uint32_t sm[];
    const int AH = 0;
    const int AL = 2 * 128 * KSTR;
    const int WH = 4 * 128 * KSTR;
    const int WL = 6 * 128 * KSTR;
    uint32_t sbase = smem_addr(sm);

    const int tid  = threadIdx.x;
    const int bm   = blockIdx.y << 7;
    const int bn   = blockIdx.x << 7;
    const int warp = tid >> 5, lane = tid & 31;
    const int wm   = warp >> 2, wn = warp & 3;      // 2 x 4 warps
    const int gid  = lane >> 2, tig = lane & 3;

    const int q = lane >> 3, rr = lane & 7;
    const int a_row = (q & 1) * 8 + rr, a_word = (q >> 1) * 4;
    const int b_row = (q >> 1) * 8 + rr, b_word = (q & 1) * 4;

    float acc[4][4][4];
#pragma unroll
    for (int i = 0; i < 4; i++)
#pragma unroll
        for (int j = 0; j < 4; j++)
#pragma unroll
            for (int qq = 0; qq < 4; qq++) acc[i][j][qq] = 0.f;

    auto load = [&](int c, int buf) {
        const int kc = c << 5;
#pragma unroll
        for (int j = 0; j < 512 / THREADS; j++) {
            int idx = tid + j * THREADS;
            int row = idx >> 2, seg = idx & 3;
            int wo = row * KSTR + seg * 4;
            size_t soA = (size_t)(bm + row) * K + kc + seg * 8;
            size_t soW = (size_t)(bn + row) * K + kc + seg * 8;
            cp16(sm + AH + buf * 128 * KSTR + wo, Ah + soA);
            cp16(sm + AL + buf * 128 * KSTR + wo, Al + soA);
            cp16(sm + WH + buf * 128 * KSTR + wo, Wh + soW);
            cp16(sm + WL + buf * 128 * KSTR + wo, Wl + soW);
        }
    };
    auto compute = [&](int buf) {
        const uint32_t a_h = sbase + 4 * (AH + buf * 128 * KSTR +
                             ((wm << 6) + a_row) * KSTR + a_word);
        const uint32_t a_l = a_h + 4 * (AL - AH);
        const uint32_t w_h = sbase + 4 * (WH + buf * 128 * KSTR +
                             ((wn << 5) + b_row) * KSTR + b_word);
        const uint32_t w_l = w_h + 4 * (WL - WH);
#pragma unroll
        for (int j = 0; j < 2; j++) {
            uint32_t ah[4][4], al[4][4], bh[4][2], bl[4][2];
#pragma unroll
            for (int mi = 0; mi < 4; mi++) {
                uint32_t off = 4 * ((mi << 4) * KSTR + (j << 3));
                ldm_x4(ah[mi], a_h + off);
                ldm_x4(al[mi], a_l + off);
            }
#pragma unroll
            for (int p = 0; p < 2; p++) {
                uint32_t off = 4 * ((p << 4) * KSTR + (j << 3));
                uint32_t t[4];
                ldm_x4(t, w_h + off);
                bh[2*p][0] = t[0]; bh[2*p][1] = t[1];
                bh[2*p+1][0] = t[2]; bh[2*p+1][1] = t[3];
                ldm_x4(t, w_l + off);
                bl[2*p][0] = t[0]; bl[2*p][1] = t[1];
                bl[2*p+1][0] = t[2]; bl[2*p+1][1] = t[3];
            }
#pragma unroll
            for (int mi = 0; mi < 4; mi++)
#pragma unroll
                for (int nj = 0; nj < 4; nj++) {
                    mma_bf16(acc[mi][nj], ah[mi], bh[nj]);
                    mma_bf16(acc[mi][nj], al[mi], bh[nj]);
                    mma_bf16(acc[mi][nj], ah[mi], bl[nj]);
                }
        }
    };

    const int NC = K >> 5;
    load(0, 0); CP_COMMIT();
    load(1, 1); CP_COMMIT();
    for (int c = 0; c < NC; c++) {
        CP_WAIT1();
        __syncthreads();
        compute(c & 1);
        __syncthreads();
        if (c + 2 < NC) load(c + 2, c & 1);
        CP_COMMIT();
    }

#pragma unroll
    for (int mi = 0; mi < 4; mi++)
#pragma unroll
        for (int nj = 0; nj < 4; nj++) {
            int row = bm + (wm << 6) + (mi << 4) + gid;
            int col = bn + (wn << 5) + (nj << 3) + (tig << 1);
            if (OUTMODE == 0) {
                *(float2*)(C + (size_t)row * N + col) =
                    make_float2(acc[mi][nj][0], acc[mi][nj][1]);
                *(float2*)(C + (size_t)(row + 8) * N + col) =
                    make_float2(acc[mi][nj][2], acc[mi][nj][3]);
            } else {
                float4 v = make_float4(acc[mi][nj][0], acc[mi][nj][1],
                                       acc[mi][nj][2], acc[mi][nj][3]);
                uint32_t h0, h1, l0, l1;
                split4(v, h0, h1, l0, l1);
                *(uint32_t*)&Ch[(size_t)row * N + col]       = h0;
                *(uint32_t*)&Ch[(size_t)(row + 8) * N + col] = h1;
                *(uint32_t*)&Cl[(size_t)row * N + col]       = l0;
                *(uint32_t*)&Cl[(size_t)(row + 8) * N + col] = l1;
            }
        }
}

static const int GSM128 = 8 * 128 * KSTR * 4;   // 81920

// --------------------- causal depthwise conv + both silus (4 chan / thread)
// also emits xs as bf16 hi/lo for the xdt GEMM.
__global__ void __launch_bounds__(256) conv_silu_k(
    const float* __restrict__ cw, const float* __restrict__ cb)
{
    int idx = blockIdx.x * 256 + threadIdx.x;   // over ROWS * DINNER/4
    int d4 = (idx & 127) << 2;
    int row = idx >> 7;
    int t = row & (SEQ - 1);

    float4 w0 = *(const float4*)(cw + ((d4 + 0) << 2));
    float4 w1 = *(const float4*)(cw + ((d4 + 1) << 2));
    float4 w2 = *(const float4*)(cw + ((d4 + 2) << 2));
    float4 w3 = *(const float4*)(cw + ((d4 + 3) << 2));
    float4 acc = *(const float4*)(cb + d4);

    if (t >= 3) {
        float4 v = *(const float4*)(&g_xz[(size_t)(row - 3) * 1024 + d4]);
        acc.x += v.x * w0.x; acc.y += v.y * w1.x;
        acc.z += v.z * w2.x; acc.w += v.w * w3.x;
    }
    if (t >= 2) {
        float4 v = *(const float4*)(&g_xz[(size_t)(row - 2) * 1024 + d4]);
        acc.x += v.x * w0.y; acc.y += v.y * w1.y;
        acc.z += v.z * w2.y; acc.w += v.w * w3.y;
    }
    if (t >= 1) {
        float4 v = *(const float4*)(&g_xz[(size_t)(row - 1) * 1024 + d4]);
        acc.x += v.x * w0.z; acc.y += v.y * w1.z;
        acc.z += v.z * w2.z; acc.w += v.w * w3.z;
    }
    {
        float4 v = *(const float4*)(&g_xz[(size_t)row * 1024 + d4]);
        acc.x += v.x * w0.w; acc.y += v.y * w1.w;
        acc.z += v.z * w2.w; acc.w += v.w * w3.w;
    }
    float4 xs4 = make_float4(siluf(acc.x), siluf(acc.y), siluf(acc.z), siluf(acc.w));
    *(float4*)(&g_xs[(size_t)row * DINNER + d4]) = xs4;
    {
        uint32_t h0, h1, l0, l1;
        split4(xs4, h0, h1, l0, l1);
        *(uint2*)&g_xsh[(size_t)row * DINNER + d4] = make_uint2(h0, h1);
        *(uint2*)&g_xsl[(size_t)row * DINNER + d4] = make_uint2(l0, l1);
    }
    float4 g = *(const float4*)(&g_xz[(size_t)row * 1024 + DINNER + d4]);
    *(float4*)(&g_gs[(size_t)row * DINNER + d4]) =
        make_float4(siluf(g.x), siluf(g.y), siluf(g.z), siluf(g.w));
}

// ------------------------------- fused x_proj + dt_proj (+softplus) kernel
// 128 CTAs x 256 thr; stage 1 pure-bf16 cp.async GEMM (A=xs, W=xp padded),
// stage 2 SIMT fp32 dt GEMM + softplus.
static const int XSTR = 68;
static const int XA_H = 0;                    // 2 x 64 x KSTR
static const int XA_L = 2 * 64 * KSTR;
static const int XW_H = 4 * 64 * KSTR;
static const int XW_L = 6 * 64 * KSTR;
static const int XSD  = 8 * 64 * KSTR;        // s_xd fp32 64 x XSTR
static const int XDT_SMEM = (XSD + 64 * XSTR) * 4;

__global__ void __launch_bounds__(256) xdt_k(
    const __nv_bfloat16* __restrict__ xph, const __nv_bfloat16* __restrict__ xpl,
    const float* __restrict__ dtw, const float* __restrict__ dtb)
{
    extern __shared__ uint32_t sm[];
    float* s_xd = (float*)(sm + XSD);
    uint32_t sbase = smem_addr(sm);

    const int tid  = threadIdx.x;
    const int row0 = blockIdx.x << 6;
    const int warp = tid >> 5, lane = tid & 31;
    const int wm   = warp >> 2, wn = warp & 3;     // 2 x 4 warps
    const int gid  = lane >> 2, tig = lane & 3;

    const int q = lane >> 3, rr = lane & 7;
    const int a_row = (q & 1) * 8 + rr, a_word = (q >> 1) * 4;
    const int b_row = (q >> 1) * 8 + rr, b_word = (q & 1) * 4;

    float acc[2][2][4];
#pragma unroll
    for (int i = 0; i < 2; i++)
#pragma unroll
        for (int j = 0; j < 2; j++)
#pragma unroll
            for (int qq = 0; qq < 4; qq++) acc[i][j][qq] = 0.f;

    auto load = [&](int c, int buf) {
        const int kc = c << 5;
        int row = tid >> 2, seg = tid & 3;
        int wo = row * KSTR + seg * 4;
        size_t soA = (size_t)(row0 + row) * DINNER + kc + seg * 8;
        size_t soW = (size_t)row * DINNER + kc + seg * 8;
        cp16(sm + XA_H + buf * 64 * KSTR + wo, g_xsh + soA);
        cp16(sm + XA_L + buf * 64 * KSTR + wo, g_xsl + soA);
        cp16(sm + XW_H + buf * 64 * KSTR + wo, xph + soW);
        cp16(sm + XW_L + buf * 64 * KSTR + wo, xpl + soW);
    };
    auto compute = [&](int buf) {
        const uint32_t a_h = sbase + 4 * (XA_H + buf * 64 * KSTR +
                             ((wm << 5) + a_row) * KSTR + a_word);
        const uint32_t a_l = a_h + 4 * (XA_L - XA_H);
        const uint32_t w_h = sbase + 4 * (XW_H + buf * 64 * KSTR +
                             ((wn << 4) + b_row) * KSTR + b_word);
        const uint32_t w_l = w_h + 4 * (XW_L - XW_H);
#pragma unroll
        for (int j = 0; j < 2; j++) {
            uint32_t ah[2][4], al[2][4], bh[2][2], bl[2][2];
#pragma unroll
            for (int mi = 0; mi < 2; mi++) {
                uint32_t off = 4 * ((mi << 4) * KSTR + (j << 3));
                ldm_x4(ah[mi], a_h + off);
                ldm_x4(al[mi], a_l + off);
            }
            {
                uint32_t off = 4 * ((j << 3));
                uint32_t t[4];
                ldm_x4(t, w_h + off);
                bh[0][0] = t[0]; bh[0][1] = t[1];
                bh[1][0] = t[2]; bh[1][1] = t[3];
                ldm_x4(t, w_l + off);
                bl[0][0] = t[0]; bl[0][1] = t[1];
                bl[1][0] = t[2]; bl[1][1] = t[3];
            }
#pragma unroll
            for (int mi = 0; mi < 2; mi++)
#pragma unroll
                for (int nj = 0; nj < 2; nj++) {
                    mma_bf16(acc[mi][nj], ah[mi], bh[nj]);
                    mma_bf16(acc[mi][nj], al[mi], bh[nj]);
                    mma_bf16(acc[mi][nj], ah[mi], bl[nj]);
                }
        }
    };

    const int NC = DINNER >> 5;   // 16
    load(0, 0); CP_COMMIT();
    load(1, 1); CP_COMMIT();
    for (int c = 0; c < NC; c++) {
        CP_WAIT1();
        __syncthreads();
        compute(c & 1);
        __syncthreads();
        if (c + 2 < NC) load(c + 2, c & 1);
        CP_COMMIT();
    }

    // epilogue: x_dbl tile -> smem (skip pad cols 48..63)
    if (wn < 3) {
#pragma unroll
        for (int mi = 0; mi < 2; mi++)
#pragma unroll
            for (int nj = 0; nj < 2; nj++) {
                int row = (wm << 5) + (mi << 4) + gid;
                int col = (wn << 4) + (nj << 3) + (tig << 1);
                s_xd[row * XSTR + col]     = acc[mi][nj][0];
                s_xd[row * XSTR + col + 1] = acc[mi][nj][1];
                s_xd[(row + 8) * XSTR + col]     = acc[mi][nj][2];
                s_xd[(row + 8) * XSTR + col + 1] = acc[mi][nj][3];
            }
    }
    __syncthreads();

    // B/C (cols 16..47) -> g_xdbl
#pragma unroll
    for (int r = 0; r < 2; r++) {
        int idx = tid + (r << 8);
        int row = idx >> 3, c = (idx & 7) << 2;
        *(float4*)(&g_xdbl[(size_t)(row0 + row) * XDBL_P + 16 + c]) =
            *(float4*)(&s_xd[row * XSTR + 16 + c]);
    }

    // dt: d = tid and tid+256, K=16 from s_xd cols 0..15 (broadcast reads)
    float wa[16], wb[16];
    {
        const float4* p1 = (const float4*)(dtw + (size_t)tid * 16);
        const float4* p2 = (const float4*)(dtw + (size_t)(tid + 256) * 16);
#pragma unroll
        for (int i = 0; i < 4; i++) {
            float4 v = p1[i];
            wa[i*4+0]=v.x; wa[i*4+1]=v.y; wa[i*4+2]=v.z; wa[i*4+3]=v.w;
            v = p2[i];
            wb[i*4+0]=v.x; wb[i*4+1]=v.y; wb[i*4+2]=v.z; wb[i*4+3]=v.w;
        }
    }
    float ba = dtb[tid], bb = dtb[tid + 256];
#pragma unroll 2
    for (int r = 0; r < 64; r++) {
        float xk[16];
#pragma unroll
        for (int i = 0; i < 4; i++) {
            float4 v = *(const float4*)(&s_xd[r * XSTR + (i << 2)]);
            xk[i*4+0]=v.x; xk[i*4+1]=v.y; xk[i*4+2]=v.z; xk[i*4+3]=v.w;
        }
        float a1 = ba, a2 = bb;
#pragma unroll
        for (int k = 0; k < 16; k++) { a1 += xk[k]*wa[k]; a2 += xk[k]*wb[k]; }
        g_dt[(size_t)(row0 + r) * DINNER + tid]       = softplusf(a1);
        g_dt[(size_t)(row0 + r) * DINNER + tid + 256] = softplusf(a2);
    }
}

// ------------------------------------------------ scan pass1: local chunks
// grid (PCHUNK-1, DINNER/16, BATCH), 128 thr = 16 d x 8 lanes (2 n each).
#define SCHUNK 64
__global__ void __launch_bounds__(128) scan_pass1(const float* __restrict__ A_log)
{
    __shared__ float s_dt[2][SCHUNK][16];
    __shared__ float s_x [2][SCHUNK][16];
    __shared__ float s_b [2][SCHUNK][16];

    const int tid = threadIdx.x;
    const int chunk = blockIdx.x, dblk = blockIdx.y, b = blockIdx.z;
    const int d0 = dblk << 4;
    const int p = tid >> 3, nl = tid & 7;
    const int d = d0 + p;

    const float A20 = -__expf(A_log[d * DSTATE + nl])     * LOG2E;
    const float A21 = -__expf(A_log[d * DSTATE + nl + 8]) * LOG2E;
    float h0 = 0.f, h1 = 0.f, sumdt = 0.f;
    const long base = (long)b * SEQ + (long)chunk * CLEN;

    auto load = [&](int cc, int buf) {
        long tb = base + (long)cc * SCHUNK;
#pragma unroll
        for (int j = 0; j < 2; j++) {
            int idx = tid + (j << 7);
            int row = idx >> 2, lq = (idx & 3) << 2;
            cp16(&s_dt[buf][row][lq], &g_dt  [(tb + row) * DINNER + d0 + lq]);
            cp16(&s_x [buf][row][lq], &g_xs  [(tb + row) * DINNER + d0 + lq]);
            cp16(&s_b [buf][row][lq], &g_xdbl[(tb + row) * XDBL_P + 16 + lq]);
        }
    };

    load(0, 0); CP_COMMIT();
    load(1, 1); CP_COMMIT();

    for (int cc = 0; cc < CLEN / SCHUNK; cc++) {
        const int buf = cc & 1;
        CP_WAIT1();
        __syncthreads();
#pragma unroll 8
        for (int i = 0; i < SCHUNK; i++) {
            float dtv = s_dt[buf][i][p];
            float xv  = s_x [buf][i][p];
            float dtx = dtv * xv;
            h0 = ex2f(dtv * A20) * h0 + dtx * s_b[buf][i][nl];
            h1 = ex2f(dtv * A21) * h1 + dtx * s_b[buf][i][nl + 8];
            sumdt += dtv;
        }
        __syncthreads();
        if (cc + 2 < CLEN / SCHUNK) load(cc + 2, buf);
        CP_COMMIT();
    }
    int o = ((b * PCHUNK + chunk) * DINNER + d) * DSTATE;
    g_hf [o + nl]     = h0;
    g_hf [o + nl + 8] = h1;
    g_dec[o + nl]     = ex2f(A20 * sumdt);
    g_dec[o + nl + 8] = ex2f(A21 * sumdt);
}

// ------------- scan pass2: inline fixup + corrected scan + y + gate mul
// grid (PCHUNK, DINNER/16, BATCH), 128 thr. Writes y as bf16 hi/lo.
__global__ void __launch_bounds__(128) scan_pass2(
    const float* __restrict__ A_log, const float* __restrict__ Dpar)
{
    __shared__ float s_dt[2][SCHUNK][16];
    __shared__ float s_x [2][SCHUNK][16];
    __shared__ float s_g [2][SCHUNK][16];
    __shared__ float s_b [2][SCHUNK][16];
    __shared__ float s_c [2][SCHUNK][16];
    __shared__ float s_y [SCHUNK][16];

    const int tid = threadIdx.x;
    const int chunk = blockIdx.x, dblk = blockIdx.y, b = blockIdx.z;
    const int d0 = dblk << 4;
    const int p = tid >> 3, nl = tid & 7;
    const int d = d0 + p;

    const float A20 = -__expf(A_log[d * DSTATE + nl])     * LOG2E;
    const float A21 = -__expf(A_log[d * DSTATE + nl + 8]) * LOG2E;
    const float Dp = Dpar[d];
    const long base = (long)b * SEQ + (long)chunk * CLEN;

    auto load = [&](int cc, int buf) {
        long tb = base + (long)cc * SCHUNK;
#pragma unroll
        for (int j = 0; j < 2; j++) {
            int idx = tid + (j << 7);
            int row = idx >> 2, lq = (idx & 3) << 2;
            cp16(&s_dt[buf][row][lq], &g_dt  [(tb + row) * DINNER + d0 + lq]);
            cp16(&s_x [buf][row][lq], &g_xs  [(tb + row) * DINNER + d0 + lq]);
            cp16(&s_g [buf][row][lq], &g_gs  [(tb + row) * DINNER + d0 + lq]);
            cp16(&s_b [buf][row][lq], &g_xdbl[(tb + row) * XDBL_P + 16 + lq]);
            cp16(&s_c [buf][row][lq], &g_xdbl[(tb + row) * XDBL_P + 32 + lq]);
        }
    };

    load(0, 0); CP_COMMIT();
    load(1, 1); CP_COMMIT();

    // inline fixup
    float h0 = 0.f, h1 = 0.f;
    for (int c = 0; c < chunk; c++) {
        int o = ((b * PCHUNK + c) * DINNER + d) * DSTATE;
        h0 = g_hf[o + nl]     + g_dec[o + nl]     * h0;
        h1 = g_hf[o + nl + 8] + g_dec[o + nl + 8] * h1;
    }

    for (int cc = 0; cc < CLEN / SCHUNK; cc++) {
        const int buf = cc & 1;
        CP_WAIT1();
        __syncthreads();
        const long outb = base + (long)cc * SCHUNK;
#pragma unroll 8
        for (int i = 0; i < SCHUNK; i++) {
            float dtv = s_dt[buf][i][p];
            float xv  = s_x [buf][i][p];
            float dtx = dtv * xv;
            h0 = ex2f(dtv * A20) * h0 + dtx * s_b[buf][i][nl];
            h1 = ex2f(dtv * A21) * h1 + dtx * s_b[buf][i][nl + 8];
            float r = h0 * s_c[buf][i][nl] + h1 * s_c[buf][i][nl + 8];
            r += __shfl_xor_sync(0xffffffffu, r, 4);
            r += __shfl_xor_sync(0xffffffffu, r, 2);
            r += __shfl_xor_sync(0xffffffffu, r, 1);
            if (nl == 0)
                s_y[i][p] = (r + xv * Dp) * s_g[buf][i][p];
        }
        __syncthreads();
        // y tile -> bf16 hi/lo, coalesced
#pragma unroll
        for (int j = 0; j < 2; j++) {
            int idx = tid + (j << 7);
            int row = idx >> 2, lq = (idx & 3) << 2;
            float4 v = *(float4*)(&s_y[row][lq]);
            uint32_t hh0, hh1, ll0, ll1;
            split4(v, hh0, hh1, ll0, ll1);
            size_t e = (size_t)(outb + row) * DINNER + d0 + lq;
            *(uint2*)&g_ygh[e] = make_uint2(hh0, hh1);
            *(uint2*)&g_ygl[e] = make_uint2(ll0, ll1);
        }
        if (cc + 2 < CLEN / SCHUNK) load(cc + 2, buf);
        CP_COMMIT();
    }
}

// ------------------------------------------------------------------- launch
extern "C" void kernel_launch(void* const* d_in, const int* in_sizes, int n_in,
                              void* d_out, int out_size)
{
    const float* z      = (const float*)d_in[0];
    const float* in_w   = (const float*)d_in[1];
    const float* conv_w = (const float*)d_in[2];
    const float* conv_b = (const float*)d_in[3];
    const float* xp_w   = (const float*)d_in[4];
    const float* dt_w   = (const float*)d_in[5];
    const float* dt_b   = (const float*)d_in[6];
    const float* A_log  = (const float*)d_in[7];
    const float* D_par  = (const float*)d_in[8];
    const float* out_w  = (const float*)d_in[9];

    float* xz;
    cudaGetSymbolAddress((void**)&xz, g_xz);

    __nv_bfloat16 *zh, *zl, *zbh, *zbl, *ygh, *ygl, *wih, *wil, *woh, *wol,
                  *xph, *xpl;
    cudaGetSymbolAddress((void**)&zh,  g_zh);
    cudaGetSymbolAddress((void**)&zl,  g_zl);
    cudaGetSymbolAddress((void**)&zbh, g_zbh);
    cudaGetSymbolAddress((void**)&zbl, g_zbl);
    cudaGetSymbolAddress((void**)&ygh, g_ygh);
    cudaGetSymbolAddress((void**)&ygl, g_ygl);
    cudaGetSymbolAddress((void**)&wih, g_wih);
    cudaGetSymbolAddress((void**)&wil, g_wil);
    cudaGetSymbolAddress((void**)&woh, g_woh);
    cudaGetSymbolAddress((void**)&wol, g_wol);
    cudaGetSymbolAddress((void**)&xph, g_xph);
    cudaGetSymbolAddress((void**)&xpl, g_xpl);

    cudaFuncSetAttribute((const void*)gemm_bb<256, 0>,
                         cudaFuncAttributeMaxDynamicSharedMemorySize, GSM128);
    cudaFuncSetAttribute((const void*)gemm_bb<256, 1>,
                         cudaFuncAttributeMaxDynamicSharedMemorySize, GSM128);
    cudaFuncSetAttribute((const void*)xdt_k,
                         cudaFuncAttributeMaxDynamicSharedMemorySize, XDT_SMEM);

    presplit_k<<<2880, 256>>>(z, in_w, out_w, xp_w);

    const dim3 p1_grid(PCHUNK - 1, DINNER / 16, BATCH);
    const dim3 p2_grid(PCHUNK,     DINNER / 16, BATCH);
    for (int l = 0; l < 2; l++) {
        const __nv_bfloat16* Ah = (l == 0) ? zh : zbh;
        const __nv_bfloat16* Al = (l == 0) ? zl : zbl;
        // in_proj: [8192,256] @ [1024,256]^T -> f32 xz
        gemm_bb<256, 0><<<dim3(8, 64), 256, GSM128>>>(
            Ah, Al, wih + (size_t)l * 1024 * DMODEL, wil + (size_t)l * 1024 * DMODEL,
            xz, nullptr, nullptr, 1024, DMODEL);
        conv_silu_k<<<(ROWS * DINNER / 4) / 256, 256>>>(
            conv_w + (size_t)l * DINNER * 4, conv_b + (size_t)l * DINNER);
        xdt_k<<<ROWS / 64, 256, XDT_SMEM>>>(
            xph + (size_t)l * 64 * DINNER, xpl + (size_t)l * 64 * DINNER,
            dt_w + (size_t)l * DINNER * 16, dt_b + (size_t)l * DINNER);
        scan_pass1<<<p1_grid, 128>>>(A_log + (size_t)l * DINNER * DSTATE);
        scan_pass2<<<p2_grid, 128>>>(
            A_log + (size_t)l * DINNER * DSTATE, D_par + (size_t)l * DINNER);
        // out_proj: [8192,512] @ [256,512]^T
        if (l == 0)
            gemm_bb<256, 1><<<dim3(2, 64), 256, GSM128>>>(
                ygh, ygl, woh, wol,
                nullptr, zbh, zbl, DMODEL, DINNER);
        else
            gemm_bb<256, 0><<<dim3(2, 64), 256, GSM128>>>(
                ygh, ygl, woh + (size_t)DMODEL * DINNER, wol + (size_t)DMODEL * DINNER,
                (float*)d_out, nullptr, nullptr, DMODEL, DINNER);
    }
}